// round 12
// baseline (speedup 1.0000x reference)
#include <cuda_runtime.h>
#include <cuda_fp16.h>
#include <math.h>
#include <stdint.h>
#include <string.h>

#define OBS_LEN 20
#define BATCH   2048
#define IN_DIM  512
#define HID     1024
#define G4      4096
#define K1      1024          // single-pass fp16: A' = fp16(h), B' = fp16(W)
#define CHUNK   32            // K per pipeline chunk
#define NCHUNK  32            // K1/CHUNK
#define TILE_M  128
#define NTILES  512           // 16 m-blocks x 32 n-tiles
#define NCTA    296           // persistent grid (<= 2 x 148 SMs, co-resident)
#define ROWB    80            // A smem row stride (64 data + 16 pad)
#define STAGE_BYTES (128 * ROWB)          // A-only stage: 10240
#define NSTAGE  4
#define SMEM_DYN (NSTAGE * STAGE_BYTES)   // 40960

// ---------------------------------------------------------------------------
// Device scratch
// ---------------------------------------------------------------------------
__device__ __align__(16) float   g_Wc[G4 * 2];
__device__ __align__(16) float   g_bc[G4];
// B in mma-fragment order: [wb=ntile*4+warpN][ktstep=0..63][lane][8 regs]
// + 64 uint4 padding (one extra kt-step) for the tail prefetch.
#define WFRAG_U4 ((size_t)128 * 64 * 32 * 2 + 64)
__device__ __align__(16) uint4   g_Wfrag[WFRAG_U4];          // ~8.4 MB
__device__ __align__(16) __half  g_A0[(size_t)BATCH * K1];   // 4.2 MB
__device__ __align__(16) __half  g_A1[(size_t)BATCH * K1];
__device__ __align__(16) float   g_cbuf[(size_t)BATCH * HID];
__device__ int g_bar_cnt;                 // monotonic grid barrier
__device__ int g_tile_cnt[OBS_LEN];       // per-step work queues

// ---------------------------------------------------------------------------
// Helpers (family-portable PTX only: cp.async / ldmatrix / mma.sync)
// ---------------------------------------------------------------------------
__device__ __forceinline__ uint32_t smem_u32(const void* p) {
    uint32_t a;
    asm("{ .reg .u64 t; cvta.to.shared.u64 t, %1; cvt.u32.u64 %0, t; }"
        : "=r"(a) : "l"(p));
    return a;
}
__device__ __forceinline__ void cp16(uint32_t dst, const void* src) {
    asm volatile("cp.async.cg.shared.global [%0], [%1], 16;"
                 :: "r"(dst), "l"(src) : "memory");
}
__device__ __forceinline__ void ldsm4(uint32_t* r, uint32_t addr) {
    asm volatile("ldmatrix.sync.aligned.m8n8.x4.shared.b16 {%0,%1,%2,%3}, [%4];"
                 : "=r"(r[0]), "=r"(r[1]), "=r"(r[2]), "=r"(r[3]) : "r"(addr));
}
__device__ __forceinline__ void mma16816(float* d, const uint32_t* a,
                                         uint32_t b0, uint32_t b1) {
    asm volatile(
        "mma.sync.aligned.m16n8k16.row.col.f32.f16.f16.f32 "
        "{%0,%1,%2,%3},{%4,%5,%6,%7},{%8,%9},{%0,%1,%2,%3};"
        : "+f"(d[0]), "+f"(d[1]), "+f"(d[2]), "+f"(d[3])
        : "r"(a[0]), "r"(a[1]), "r"(a[2]), "r"(a[3]), "r"(b0), "r"(b1));
}
__device__ __forceinline__ float sigm(float x) {
    return __fdividef(1.f, 1.f + __expf(-x));
}
__device__ __forceinline__ float tanh_f(float x) {
    return __fdividef(2.f, 1.f + __expf(-2.f * x)) - 1.f;
}

// ---------------------------------------------------------------------------
// Prep 1: fold embedding into per-gate input weights (Wc [G4][2], bc [G4]).
// ---------------------------------------------------------------------------
__global__ void prep_wc_kernel(const float* __restrict__ W_emb,
                               const float* __restrict__ b_emb,
                               const float* __restrict__ W_ih,
                               const float* __restrict__ b_ih,
                               const float* __restrict__ b_hh) {
    int warp = (blockIdx.x * blockDim.x + threadIdx.x) >> 5;
    int lane = threadIdx.x & 31;
    if (warp >= G4) return;
    const float* wrow = W_ih + (size_t)warp * IN_DIM;
    float s0 = 0.f, s1 = 0.f, sb = 0.f;
    for (int h = lane; h < IN_DIM; h += 32) {
        float w = wrow[h];
        s0 += w * W_emb[h * 2 + 0];
        s1 += w * W_emb[h * 2 + 1];
        sb += w * b_emb[h];
    }
#pragma unroll
    for (int o = 16; o > 0; o >>= 1) {
        s0 += __shfl_down_sync(0xffffffffu, s0, o);
        s1 += __shfl_down_sync(0xffffffffu, s1, o);
        sb += __shfl_down_sync(0xffffffffu, sb, o);
    }
    if (lane == 0) {
        g_Wc[warp * 2 + 0] = s0;
        g_Wc[warp * 2 + 1] = s1;
        g_bc[warp] = sb + b_ih[warp] + b_hh[warp];
    }
}

// ---------------------------------------------------------------------------
// Prep 2: build B' = fp16(W_hh) in exact mma b-fragment order.
// 512 blocks: wb = blockIdx.x>>2 handles quarter (blockIdx.x&3) of v-range.
// ---------------------------------------------------------------------------
__global__ void prep_wfrag_kernel(const float* __restrict__ W_hh) {
    int wb = blockIdx.x >> 2;              // 0..127
    int vbase = (blockIdx.x & 3) * 4096;   // quarter of 16384
    int ntile = wb >> 2, warpN = wb & 3;
    uint32_t* out = (uint32_t*)g_Wfrag + (size_t)wb * 16384;
    for (int v = vbase + threadIdx.x; v < vbase + 4096; v += blockDim.x) {
        int reg   = v & 7;
        int lane  = (v >> 3) & 31;
        int kts   = v >> 8;                // 0..63
        int nb = reg >> 1, half = reg & 1;
        int unit = ntile * 32 + warpN * 8 + (lane >> 2);
        int j = (nb << 10) + unit;
        int kbase = kts * 16 + half * 8 + (lane & 3) * 2;
        uint32_t pack = 0;
#pragma unroll
        for (int i = 0; i < 2; i++) {
            __half o = __float2half(W_hh[(size_t)j * HID + kbase + i]);
            unsigned short us;
            memcpy(&us, &o, 2);
            pack |= (uint32_t)us << (16 * i);
        }
        out[v] = pack;
    }
}

// ---------------------------------------------------------------------------
// Prep 3: h0 -> A'(step 0) = fp16(h0); block 0 also zeroes barrier/queues.
// ---------------------------------------------------------------------------
__global__ void init_h0_kernel(const float* __restrict__ h0) {
    if (blockIdx.x == 0 && threadIdx.x <= OBS_LEN) {
        if (threadIdx.x == OBS_LEN) g_bar_cnt = 0;
        else                        g_tile_cnt[threadIdx.x] = 0;
    }
    int v = blockIdx.x * blockDim.x + threadIdx.x;
    int e = v * 4;
    float4 h = *(const float4*)(h0 + e);
    float vv[4] = {h.x, h.y, h.z, h.w};
    union { __half b[4]; uint2 u2; } phi;
#pragma unroll
    for (int x = 0; x < 4; x++) phi.b[x] = __float2half(vv[x]);
    *(uint2*)(g_A0 + e) = phi.u2;
}

// ---------------------------------------------------------------------------
// One 128x128 tile: HMMA GEMM over K=1024 + fused LSTM cell (R11 mainloop,
// byte-identical schedule). tile = mblock + 16*ntile.
// ---------------------------------------------------------------------------
__device__ __forceinline__ void process_tile(
    int tile, const __half* __restrict__ Acur, __half* __restrict__ Anext,
    const float* __restrict__ cin, const float* __restrict__ obs_t,
    float* __restrict__ hout,
    uint32_t base, uint32_t aoff, int tid, int lane, int warpM, int warpN) {
    const int mblock = tile & 15;
    const int ntile  = tile >> 4;
    const int bRow = mblock * TILE_M;

    float acc[4][4][4];
#pragma unroll
    for (int m = 0; m < 4; m++)
#pragma unroll
        for (int n = 0; n < 4; n++)
#pragma unroll
            for (int x = 0; x < 4; x++) acc[m][n][x] = 0.f;

    // A loader: thread covers 32B of row lr at col half lc
    const int lr = tid >> 1;
    const int lc = (tid & 1) * 2;
    const __half* asrc = Acur + (size_t)(bRow + lr) * K1 + lc * 8;
    const uint32_t adst = base + lr * ROWB + lc * 16;

    // B fragment stream pointer: advances 64 uint4 (1KB) per kt-step
    const uint4* bp = g_Wfrag
        + ((size_t)(ntile * 4 + warpN) * 64 * 32 + lane) * 2;

    // Preload B for kt-step 0
    uint32_t bR[2][8];
    {
        uint4 t0 = bp[0], t1 = bp[1];
        bp += 64;
        bR[0][0] = t0.x; bR[0][1] = t0.y; bR[0][2] = t0.z; bR[0][3] = t0.w;
        bR[0][4] = t1.x; bR[0][5] = t1.y; bR[0][6] = t1.z; bR[0][7] = t1.w;
    }

    // Prologue: A chunks 0..2 into stages 0..2
#pragma unroll
    for (int s = 0; s < NSTAGE - 1; s++) {
        uint32_t so = s * STAGE_BYTES;
        int k0 = s * CHUNK;
        cp16(adst + so, asrc + k0);
        cp16(adst + so + 16, asrc + k0 + 8);
        asm volatile("cp.async.commit_group;" ::: "memory");
    }

#pragma unroll 4
    for (int it = 0; it < NCHUNK; ++it) {
        asm volatile("cp.async.wait_group 2;" ::: "memory");
        __syncthreads();
        const uint32_t so = (uint32_t)(it & (NSTAGE - 1)) * STAGE_BYTES;

        // Prefetch A chunk it+3
        {
            int nl = it + NSTAGE - 1;
            if (nl < NCHUNK) {
                uint32_t so2 = (uint32_t)(nl & (NSTAGE - 1)) * STAGE_BYTES;
                int k0 = nl * CHUNK;
                cp16(adst + so2, asrc + k0);
                cp16(adst + so2 + 16, asrc + k0 + 8);
            }
            asm volatile("cp.async.commit_group;" ::: "memory");
        }

#pragma unroll
        for (int kt = 0; kt < 2; kt++) {
            const int cur = (it * 2 + kt) & 1, nxt = cur ^ 1;

            // Prefetch next kt-step's B fragments (1KB/warp, L2-resident).
            uint4 t0 = bp[0], t1 = bp[1];
            bp += 64;

            // A fragments for this kt
            uint32_t aF[4][4];
            const uint32_t aA = base + so + aoff + kt * 32;
#pragma unroll
            for (int m = 0; m < 4; m++) ldsm4(aF[m], aA + m * 16 * ROWB);

#pragma unroll
            for (int m = 0; m < 4; m++)
#pragma unroll
                for (int n = 0; n < 4; n++)
                    mma16816(acc[m][n], aF[m], bR[cur][n * 2], bR[cur][n * 2 + 1]);

            bR[nxt][0] = t0.x; bR[nxt][1] = t0.y; bR[nxt][2] = t0.z; bR[nxt][3] = t0.w;
            bR[nxt][4] = t1.x; bR[nxt][5] = t1.y; bR[nxt][6] = t1.z; bR[nxt][7] = t1.w;
        }
    }

    // ------------------ fused LSTM epilogue (all in registers) ------------------
    const int q = lane & 3;
    const int u0 = ntile * 32 + warpN * 8 + 2 * q;       // 2 units: u0, u0+1
    const int rbase = bRow + warpM * 64 + (lane >> 2);

    float wcx[2][4], wcy[2][4], bcv[2][4];
#pragma unroll
    for (int i = 0; i < 2; i++)
#pragma unroll
        for (int gg = 0; gg < 4; gg++) {
            int j = (gg << 10) + u0 + i;
            float2 w = *(const float2*)(g_Wc + j * 2);
            wcx[i][gg] = w.x; wcy[i][gg] = w.y; bcv[i][gg] = g_bc[j];
        }

#pragma unroll
    for (int m = 0; m < 4; m++)
#pragma unroll
        for (int s = 0; s < 2; s++) {
            int b = rbase + m * 16 + s * 8;
            float2 ob = *(const float2*)(obs_t + b * 2);
            float2 cold = *(const float2*)(cin + (size_t)b * HID + u0);
            float cprev[2] = {cold.x, cold.y};
            float cn[2], hn[2];
#pragma unroll
            for (int i = 0; i < 2; i++) {
                float gv[4];
#pragma unroll
                for (int gg = 0; gg < 4; gg++)
                    gv[gg] = acc[m][gg][s * 2 + i]
                           + ob.x * wcx[i][gg] + ob.y * wcy[i][gg] + bcv[i][gg];
                float ig = sigm(gv[0]);
                float fg = sigm(gv[1]);
                float gc = tanh_f(gv[2]);
                float og = sigm(gv[3]);
                cn[i] = fg * cprev[i] + ig * gc;
                hn[i] = og * tanh_f(cn[i]);
            }
            *(float2*)(g_cbuf + (size_t)b * HID + u0) = make_float2(cn[0], cn[1]);
            if (hout)
                *(float2*)(hout + (size_t)b * HID + u0) = make_float2(hn[0], hn[1]);

            if (Anext) {
                union { __half h[2]; uint32_t u; } phi;
#pragma unroll
                for (int i = 0; i < 2; i++) phi.h[i] = __float2half(hn[i]);
                *(uint32_t*)(Anext + (size_t)b * K1 + u0) = phi.u;
            }
        }
}

// ---------------------------------------------------------------------------
// Persistent kernel: all 20 LSTM steps, per-step tile work-queue + grid barrier.
// ---------------------------------------------------------------------------
__global__ __launch_bounds__(256, 2) void lstm_persist_kernel(
    const float* __restrict__ c0,
    const float* __restrict__ obs,
    float* __restrict__ d_out) {
    extern __shared__ __align__(128) char dyn[];
    __shared__ int s_tile;
    const int tid = threadIdx.x;
    const int wid = tid >> 5, lane = tid & 31;
    const int warpM = wid >> 2, warpN = wid & 3;   // 2 x 4 warp grid
    const uint32_t base = smem_u32(dyn);

    // A ldmatrix per-thread address (tile-independent part)
    const int g = lane >> 3, jj = lane & 7;
    const uint32_t aoff = (uint32_t)((warpM * 64 + ((g & 1) << 3) + jj) * ROWB
                                     + ((g >> 1) << 4));

    for (int step = 0; step < OBS_LEN; ++step) {
        const __half* Acur = (step & 1) ? g_A1 : g_A0;
        __half* Anext = (step == OBS_LEN - 1) ? (__half*)0
                       : ((step & 1) ? g_A0 : g_A1);
        const float* cin = (step == 0) ? c0 : g_cbuf;
        const float* obs_t = obs + (size_t)step * BATCH * 2;
        float* hout = (step == OBS_LEN - 1) ? d_out : (float*)0;

        // work-stealing over the 512 tiles of this step
        for (;;) {
            if (tid == 0) s_tile = atomicAdd(&g_tile_cnt[step], 1);
            __syncthreads();
            int tile = s_tile;
            if (tile >= NTILES) break;
            process_tile(tile, Acur, Anext, cin, obs_t, hout,
                         base, aoff, tid, lane, warpM, warpN);
        }

        // grid barrier: monotonic counter, release via threadfence
        __threadfence();
        __syncthreads();
        if (tid == 0) {
            atomicAdd(&g_bar_cnt, 1);
            while (atomicAdd(&g_bar_cnt, 0) < NCTA * (step + 1))
                __nanosleep(128);
        }
        __syncthreads();
    }
}

// ---------------------------------------------------------------------------
extern "C" void kernel_launch(void* const* d_in, const int* in_sizes, int n_in,
                              void* d_out, int out_size) {
    const float* obs   = (const float*)d_in[0];
    const float* h0    = (const float*)d_in[1];
    const float* c0    = (const float*)d_in[2];
    const float* W_emb = (const float*)d_in[3];
    const float* b_emb = (const float*)d_in[4];
    const float* W_ih  = (const float*)d_in[5];
    const float* W_hh  = (const float*)d_in[6];
    const float* b_ih  = (const float*)d_in[7];
    const float* b_hh  = (const float*)d_in[8];

    prep_wc_kernel<<<512, 256>>>(W_emb, b_emb, W_ih, b_ih, b_hh);
    prep_wfrag_kernel<<<512, 256>>>(W_hh);
    init_h0_kernel<<<BATCH * HID / 4 / 256, 256>>>(h0);

    cudaFuncSetAttribute(lstm_persist_kernel,
                         cudaFuncAttributeMaxDynamicSharedMemorySize, SMEM_DYN);

    lstm_persist_kernel<<<NCTA, 256, SMEM_DYN>>>(c0, obs, (float*)d_out);
}

// round 13
// speedup vs baseline: 1.4622x; 1.4622x over previous
#include <cuda_runtime.h>
#include <cuda_fp16.h>
#include <math.h>
#include <stdint.h>
#include <string.h>

#define OBS_LEN 20
#define BATCH   2048
#define IN_DIM  512
#define HID     1024
#define G4      4096
#define K1      1024          // single-pass fp16: A' = fp16(h), B' = fp16(W)
#define CHUNK   32            // K per pipeline chunk
#define NCHUNK  32            // K1/CHUNK
#define TILE_M  128
#define ROWB    80            // A smem row stride (64 data + 16 pad)
#define STAGE_BYTES (128 * ROWB)          // A-only stage: 10240
#define NSTAGE  4
#define SMEM_DYN (NSTAGE * STAGE_BYTES)   // 40960

// ---------------------------------------------------------------------------
// Device scratch
// ---------------------------------------------------------------------------
__device__ __align__(16) float   g_Wc[G4 * 2];
__device__ __align__(16) float   g_bc[G4];
// B in mma-fragment order: [wb=ntile*4+warpN][ktstep=0..63][lane][8 regs]
// + 64 uint4 padding (one extra kt-step) for the tail prefetch.
#define WFRAG_U4 ((size_t)128 * 64 * 32 * 2 + 64)
__device__ __align__(16) uint4   g_Wfrag[WFRAG_U4];          // ~8.4 MB
__device__ __align__(16) __half  g_A0[(size_t)BATCH * K1];   // 4.2 MB
__device__ __align__(16) __half  g_A1[(size_t)BATCH * K1];
__device__ __align__(16) float   g_cbuf[(size_t)BATCH * HID];

// ---------------------------------------------------------------------------
// Helpers (family-portable PTX only: cp.async / ldmatrix / mma.sync)
// ---------------------------------------------------------------------------
__device__ __forceinline__ uint32_t smem_u32(const void* p) {
    uint32_t a;
    asm("{ .reg .u64 t; cvta.to.shared.u64 t, %1; cvt.u32.u64 %0, t; }"
        : "=r"(a) : "l"(p));
    return a;
}
__device__ __forceinline__ void cp16(uint32_t dst, const void* src) {
    asm volatile("cp.async.cg.shared.global [%0], [%1], 16;"
                 :: "r"(dst), "l"(src) : "memory");
}
__device__ __forceinline__ void ldsm4(uint32_t* r, uint32_t addr) {
    asm volatile("ldmatrix.sync.aligned.m8n8.x4.shared.b16 {%0,%1,%2,%3}, [%4];"
                 : "=r"(r[0]), "=r"(r[1]), "=r"(r[2]), "=r"(r[3]) : "r"(addr));
}
__device__ __forceinline__ void mma16816(float* d, const uint32_t* a,
                                         uint32_t b0, uint32_t b1) {
    asm volatile(
        "mma.sync.aligned.m16n8k16.row.col.f32.f16.f16.f32 "
        "{%0,%1,%2,%3},{%4,%5,%6,%7},{%8,%9},{%0,%1,%2,%3};"
        : "+f"(d[0]), "+f"(d[1]), "+f"(d[2]), "+f"(d[3])
        : "r"(a[0]), "r"(a[1]), "r"(a[2]), "r"(a[3]), "r"(b0), "r"(b1));
}
__device__ __forceinline__ float sigm(float x) {
    return __fdividef(1.f, 1.f + __expf(-x));
}
__device__ __forceinline__ float tanh_f(float x) {
    return __fdividef(2.f, 1.f + __expf(-2.f * x)) - 1.f;
}

// ---------------------------------------------------------------------------
// Merged prep (one launch, 3072 blocks x 256):
//   blocks [0,512)     : fold embedding -> Wc [G4][2], bc [G4]
//   blocks [512,1024)  : B' = fp16(W_hh) in exact mma b-fragment order
//   blocks [1024,3072) : A'(step 0) = fp16(h0)
// All three parts are mutually independent.
// ---------------------------------------------------------------------------
__global__ void prep_all_kernel(const float* __restrict__ W_emb,
                                const float* __restrict__ b_emb,
                                const float* __restrict__ W_ih,
                                const float* __restrict__ b_ih,
                                const float* __restrict__ b_hh,
                                const float* __restrict__ W_hh,
                                const float* __restrict__ h0) {
    if (blockIdx.x < 512) {
        // ---- prep_wc: one warp per output row j ----
        int warp = (blockIdx.x * blockDim.x + threadIdx.x) >> 5;
        int lane = threadIdx.x & 31;
        if (warp >= G4) return;
        const float* wrow = W_ih + (size_t)warp * IN_DIM;
        float s0 = 0.f, s1 = 0.f, sb = 0.f;
        for (int h = lane; h < IN_DIM; h += 32) {
            float w = wrow[h];
            s0 += w * W_emb[h * 2 + 0];
            s1 += w * W_emb[h * 2 + 1];
            sb += w * b_emb[h];
        }
#pragma unroll
        for (int o = 16; o > 0; o >>= 1) {
            s0 += __shfl_down_sync(0xffffffffu, s0, o);
            s1 += __shfl_down_sync(0xffffffffu, s1, o);
            sb += __shfl_down_sync(0xffffffffu, sb, o);
        }
        if (lane == 0) {
            g_Wc[warp * 2 + 0] = s0;
            g_Wc[warp * 2 + 1] = s1;
            g_bc[warp] = sb + b_ih[warp] + b_hh[warp];
        }
    } else if (blockIdx.x < 1024) {
        // ---- prep_wfrag: wb = bid>>2 handles quarter (bid&3) of v-range ----
        int bid = blockIdx.x - 512;
        int wb = bid >> 2;                 // 0..127
        int vbase = (bid & 3) * 4096;      // quarter of 16384
        int ntile = wb >> 2, warpN = wb & 3;
        uint32_t* out = (uint32_t*)g_Wfrag + (size_t)wb * 16384;
        for (int v = vbase + threadIdx.x; v < vbase + 4096; v += blockDim.x) {
            int reg   = v & 7;
            int lane  = (v >> 3) & 31;
            int kts   = v >> 8;            // 0..63
            int nb = reg >> 1, half = reg & 1;
            int unit = ntile * 32 + warpN * 8 + (lane >> 2);
            int j = (nb << 10) + unit;
            int kbase = kts * 16 + half * 8 + (lane & 3) * 2;
            uint32_t pack = 0;
#pragma unroll
            for (int i = 0; i < 2; i++) {
                __half o = __float2half(W_hh[(size_t)j * HID + kbase + i]);
                unsigned short us;
                memcpy(&us, &o, 2);
                pack |= (uint32_t)us << (16 * i);
            }
            out[v] = pack;
        }
    } else {
        // ---- init_h0: A'(step 0) = fp16(h0) ----
        int v = (blockIdx.x - 1024) * blockDim.x + threadIdx.x;
        int e = v * 4;
        float4 h = *(const float4*)(h0 + e);
        float vv[4] = {h.x, h.y, h.z, h.w};
        union { __half b[4]; uint2 u2; } phi;
#pragma unroll
        for (int x = 0; x < 4; x++) phi.b[x] = __float2half(vv[x]);
        *(uint2*)(g_A0 + e) = phi.u2;
    }
}

// ---------------------------------------------------------------------------
// Fused LSTM step: 128x128 HMMA GEMM over K=1024 + in-register cell update.
// 8 warps (2Mx4N, warp tile 64x32), CHUNK=32, NSTAGE=4, B streamed from
// gmem in fragment order, single-pass fp16. cin = c0 (step 0) or g_cbuf.
// ---------------------------------------------------------------------------
__global__ __launch_bounds__(256, 2) void lstm_step_kernel(
    const __half* __restrict__ Acur,
    __half* __restrict__ Anext,          // nullptr on last step
    const float* __restrict__ cin,       // c0 (t=0) or g_cbuf
    const float* __restrict__ obs_t,
    float* __restrict__ hout) {
    extern __shared__ __align__(128) char dyn[];
    const int tid = threadIdx.x;
    const int wid = tid >> 5, lane = tid & 31;
    const int warpM = wid >> 2, warpN = wid & 3;   // 2 x 4 warp grid
    const int bRow = blockIdx.x * TILE_M;

    const uint32_t base = smem_u32(dyn);

    // A ldmatrix per-thread address: rows (g&1)*8+jj of warp's 64, 16B half g>>1
    const int g = lane >> 3, jj = lane & 7;
    const uint32_t aoff = (uint32_t)((warpM * 64 + ((g & 1) << 3) + jj) * ROWB
                                     + ((g >> 1) << 4));

    float acc[4][4][4];
#pragma unroll
    for (int m = 0; m < 4; m++)
#pragma unroll
        for (int n = 0; n < 4; n++)
#pragma unroll
            for (int x = 0; x < 4; x++) acc[m][n][x] = 0.f;

    // A loader: thread covers 32B of row lr at col half lc
    const int lr = tid >> 1;
    const int lc = (tid & 1) * 2;
    const __half* asrc = Acur + (size_t)(bRow + lr) * K1 + lc * 8;
    const uint32_t adst = base + lr * ROWB + lc * 16;

    // B fragment stream pointer: advances 64 uint4 (1KB) per kt-step
    const uint4* bp = g_Wfrag
        + ((size_t)(blockIdx.y * 4 + warpN) * 64 * 32 + lane) * 2;

    // Preload B for kt-step 0
    uint32_t bR[2][8];
    {
        uint4 t0 = bp[0], t1 = bp[1];
        bp += 64;
        bR[0][0] = t0.x; bR[0][1] = t0.y; bR[0][2] = t0.z; bR[0][3] = t0.w;
        bR[0][4] = t1.x; bR[0][5] = t1.y; bR[0][6] = t1.z; bR[0][7] = t1.w;
    }

    // Prologue: A chunks 0..2 into stages 0..2
#pragma unroll
    for (int s = 0; s < NSTAGE - 1; s++) {
        uint32_t so = s * STAGE_BYTES;
        int k0 = s * CHUNK;
        cp16(adst + so, asrc + k0);
        cp16(adst + so + 16, asrc + k0 + 8);
        asm volatile("cp.async.commit_group;" ::: "memory");
    }

#pragma unroll 4
    for (int it = 0; it < NCHUNK; ++it) {
        asm volatile("cp.async.wait_group 2;" ::: "memory");
        __syncthreads();
        const uint32_t so = (uint32_t)(it & (NSTAGE - 1)) * STAGE_BYTES;

        // Prefetch A chunk it+3
        {
            int nl = it + NSTAGE - 1;
            if (nl < NCHUNK) {
                uint32_t so2 = (uint32_t)(nl & (NSTAGE - 1)) * STAGE_BYTES;
                int k0 = nl * CHUNK;
                cp16(adst + so2, asrc + k0);
                cp16(adst + so2 + 16, asrc + k0 + 8);
            }
            asm volatile("cp.async.commit_group;" ::: "memory");
        }

#pragma unroll
        for (int kt = 0; kt < 2; kt++) {
            const int cur = (it * 2 + kt) & 1, nxt = cur ^ 1;

            // Prefetch next kt-step's B fragments (1KB/warp, L2-resident).
            // Padding at the end of g_Wfrag covers the final over-read.
            uint4 t0 = bp[0], t1 = bp[1];
            bp += 64;

            // A fragments for this kt
            uint32_t aF[4][4];
            const uint32_t aA = base + so + aoff + kt * 32;
#pragma unroll
            for (int m = 0; m < 4; m++) ldsm4(aF[m], aA + m * 16 * ROWB);

#pragma unroll
            for (int m = 0; m < 4; m++)
#pragma unroll
                for (int n = 0; n < 4; n++)
                    mma16816(acc[m][n], aF[m], bR[cur][n * 2], bR[cur][n * 2 + 1]);

            bR[nxt][0] = t0.x; bR[nxt][1] = t0.y; bR[nxt][2] = t0.z; bR[nxt][3] = t0.w;
            bR[nxt][4] = t1.x; bR[nxt][5] = t1.y; bR[nxt][6] = t1.z; bR[nxt][7] = t1.w;
        }
    }

    // ------------------ fused LSTM epilogue (all in registers) ------------------
    const int q = lane & 3;
    const int u0 = blockIdx.y * 32 + warpN * 8 + 2 * q;    // 2 units: u0, u0+1
    const int rbase = bRow + warpM * 64 + (lane >> 2);

    float wcx[2][4], wcy[2][4], bcv[2][4];
#pragma unroll
    for (int i = 0; i < 2; i++)
#pragma unroll
        for (int gg = 0; gg < 4; gg++) {
            int j = (gg << 10) + u0 + i;
            float2 w = *(const float2*)(g_Wc + j * 2);
            wcx[i][gg] = w.x; wcy[i][gg] = w.y; bcv[i][gg] = g_bc[j];
        }

#pragma unroll
    for (int m = 0; m < 4; m++)
#pragma unroll
        for (int s = 0; s < 2; s++) {
            int b = rbase + m * 16 + s * 8;
            float2 ob = *(const float2*)(obs_t + b * 2);
            float2 cold = *(const float2*)(cin + (size_t)b * HID + u0);
            float cprev[2] = {cold.x, cold.y};
            float cn[2], hn[2];
#pragma unroll
            for (int i = 0; i < 2; i++) {
                float gv[4];
#pragma unroll
                for (int gg = 0; gg < 4; gg++)
                    gv[gg] = acc[m][gg][s * 2 + i]
                           + ob.x * wcx[i][gg] + ob.y * wcy[i][gg] + bcv[i][gg];
                float ig = sigm(gv[0]);
                float fg = sigm(gv[1]);
                float gc = tanh_f(gv[2]);
                float og = sigm(gv[3]);
                cn[i] = fg * cprev[i] + ig * gc;
                hn[i] = og * tanh_f(cn[i]);
            }
            *(float2*)(g_cbuf + (size_t)b * HID + u0) = make_float2(cn[0], cn[1]);
            if (hout)
                *(float2*)(hout + (size_t)b * HID + u0) = make_float2(hn[0], hn[1]);

            if (Anext) {
                union { __half h[2]; uint32_t u; } phi;
#pragma unroll
                for (int i = 0; i < 2; i++) phi.h[i] = __float2half(hn[i]);
                *(uint32_t*)(Anext + (size_t)b * K1 + u0) = phi.u;
            }
        }
}

// ---------------------------------------------------------------------------
extern "C" void kernel_launch(void* const* d_in, const int* in_sizes, int n_in,
                              void* d_out, int out_size) {
    const float* obs   = (const float*)d_in[0];
    const float* h0    = (const float*)d_in[1];
    const float* c0    = (const float*)d_in[2];
    const float* W_emb = (const float*)d_in[3];
    const float* b_emb = (const float*)d_in[4];
    const float* W_ih  = (const float*)d_in[5];
    const float* W_hh  = (const float*)d_in[6];
    const float* b_ih  = (const float*)d_in[7];
    const float* b_hh  = (const float*)d_in[8];

    float* cbuf;
    __half *a0, *a1;
    cudaGetSymbolAddress((void**)&cbuf, g_cbuf);
    cudaGetSymbolAddress((void**)&a0, g_A0);
    cudaGetSymbolAddress((void**)&a1, g_A1);

    prep_all_kernel<<<3072, 256>>>(W_emb, b_emb, W_ih, b_ih, b_hh, W_hh, h0);

    cudaFuncSetAttribute(lstm_step_kernel,
                         cudaFuncAttributeMaxDynamicSharedMemorySize, SMEM_DYN);

    dim3 grid(BATCH / TILE_M, HID / 32);   // (16, 32)
    __half* bufs[2] = {a0, a1};
    for (int t = 0; t < OBS_LEN; t++) {
        const float* cin = (t == 0) ? c0 : cbuf;
        __half* Anext = (t == OBS_LEN - 1) ? nullptr : bufs[(t + 1) & 1];
        lstm_step_kernel<<<grid, 256, SMEM_DYN>>>(
            bufs[t & 1], Anext, cin,
            obs + (size_t)t * BATCH * 2,
            (t == OBS_LEN - 1) ? (float*)d_out : nullptr);
    }
}

// round 14
// speedup vs baseline: 1.5138x; 1.0353x over previous
#include <cuda_runtime.h>
#include <cuda_fp16.h>
#include <math.h>
#include <stdint.h>
#include <string.h>

#define OBS_LEN 20
#define BATCH   2048
#define IN_DIM  512
#define HID     1024
#define G4      4096
#define K1      1024          // single-pass fp16: A' = fp16(h), B' = fp16(W)
#define CHUNK   32            // K per pipeline chunk
#define NCHUNK  32            // K1/CHUNK
#define TILE_M  128
#define ROWB    80            // A smem row stride (64 data + 16 pad)
#define STAGE_BYTES (128 * ROWB)          // A-only stage: 10240
#define NSTAGE  4
#define SMEM_DYN (NSTAGE * STAGE_BYTES)   // 40960

// ---------------------------------------------------------------------------
// Device scratch
// ---------------------------------------------------------------------------
__device__ __align__(16) float   g_Wc[G4 * 2];
__device__ __align__(16) float   g_bc[G4];
// B in mma-fragment order: [wb=ntile*4+warpN][ktstep=0..63][lane][8 regs]
// + 64 uint4 padding (one extra kt-step) for the tail prefetch.
#define WFRAG_U4 ((size_t)128 * 64 * 32 * 2 + 64)
__device__ __align__(16) uint4   g_Wfrag[WFRAG_U4];          // ~8.4 MB
__device__ __align__(16) __half  g_A0[(size_t)BATCH * K1];   // 4.2 MB
__device__ __align__(16) __half  g_A1[(size_t)BATCH * K1];
__device__ __align__(16) float   g_cbuf[(size_t)BATCH * HID];

// ---------------------------------------------------------------------------
// Helpers (family-portable PTX only: cp.async / ldmatrix / mma.sync / tanh.approx)
// ---------------------------------------------------------------------------
__device__ __forceinline__ uint32_t smem_u32(const void* p) {
    uint32_t a;
    asm("{ .reg .u64 t; cvta.to.shared.u64 t, %1; cvt.u32.u64 %0, t; }"
        : "=r"(a) : "l"(p));
    return a;
}
__device__ __forceinline__ void cp16(uint32_t dst, const void* src) {
    asm volatile("cp.async.cg.shared.global [%0], [%1], 16;"
                 :: "r"(dst), "l"(src) : "memory");
}
__device__ __forceinline__ void ldsm4(uint32_t* r, uint32_t addr) {
    asm volatile("ldmatrix.sync.aligned.m8n8.x4.shared.b16 {%0,%1,%2,%3}, [%4];"
                 : "=r"(r[0]), "=r"(r[1]), "=r"(r[2]), "=r"(r[3]) : "r"(addr));
}
__device__ __forceinline__ void mma16816(float* d, const uint32_t* a,
                                         uint32_t b0, uint32_t b1) {
    asm volatile(
        "mma.sync.aligned.m16n8k16.row.col.f32.f16.f16.f32 "
        "{%0,%1,%2,%3},{%4,%5,%6,%7},{%8,%9},{%0,%1,%2,%3};"
        : "+f"(d[0]), "+f"(d[1]), "+f"(d[2]), "+f"(d[3])
        : "r"(a[0]), "r"(a[1]), "r"(a[2]), "r"(a[3]), "r"(b0), "r"(b1));
}
// HW tanh unit (MUFU.TANH, sm_75+): 1 MUFU op, ~2^-11 rel accuracy.
__device__ __forceinline__ float tanh_ap(float x) {
    float y;
    asm("tanh.approx.f32 %0, %1;" : "=f"(y) : "f"(x));
    return y;
}
__device__ __forceinline__ float sigm(float x) {
    return fmaf(0.5f, tanh_ap(0.5f * x), 0.5f);
}
__device__ __forceinline__ float tanh_f(float x) { return tanh_ap(x); }

// ---------------------------------------------------------------------------
// Merged prep (one launch, 3072 blocks x 256):
//   blocks [0,512)     : fold embedding -> Wc [G4][2], bc [G4]
//   blocks [512,1024)  : B' = fp16(W_hh) in exact mma b-fragment order
//   blocks [1024,3072) : A'(step 0) = fp16(h0)
// All three parts are mutually independent.
// ---------------------------------------------------------------------------
__global__ void prep_all_kernel(const float* __restrict__ W_emb,
                                const float* __restrict__ b_emb,
                                const float* __restrict__ W_ih,
                                const float* __restrict__ b_ih,
                                const float* __restrict__ b_hh,
                                const float* __restrict__ W_hh,
                                const float* __restrict__ h0) {
    if (blockIdx.x < 512) {
        // ---- prep_wc: one warp per output row j ----
        int warp = (blockIdx.x * blockDim.x + threadIdx.x) >> 5;
        int lane = threadIdx.x & 31;
        if (warp >= G4) return;
        const float* wrow = W_ih + (size_t)warp * IN_DIM;
        float s0 = 0.f, s1 = 0.f, sb = 0.f;
        for (int h = lane; h < IN_DIM; h += 32) {
            float w = wrow[h];
            s0 += w * W_emb[h * 2 + 0];
            s1 += w * W_emb[h * 2 + 1];
            sb += w * b_emb[h];
        }
#pragma unroll
        for (int o = 16; o > 0; o >>= 1) {
            s0 += __shfl_down_sync(0xffffffffu, s0, o);
            s1 += __shfl_down_sync(0xffffffffu, s1, o);
            sb += __shfl_down_sync(0xffffffffu, sb, o);
        }
        if (lane == 0) {
            g_Wc[warp * 2 + 0] = s0;
            g_Wc[warp * 2 + 1] = s1;
            g_bc[warp] = sb + b_ih[warp] + b_hh[warp];
        }
    } else if (blockIdx.x < 1024) {
        // ---- prep_wfrag: wb = bid>>2 handles quarter (bid&3) of v-range ----
        int bid = blockIdx.x - 512;
        int wb = bid >> 2;                 // 0..127
        int vbase = (bid & 3) * 4096;      // quarter of 16384
        int ntile = wb >> 2, warpN = wb & 3;
        uint32_t* out = (uint32_t*)g_Wfrag + (size_t)wb * 16384;
        for (int v = vbase + threadIdx.x; v < vbase + 4096; v += blockDim.x) {
            int reg   = v & 7;
            int lane  = (v >> 3) & 31;
            int kts   = v >> 8;            // 0..63
            int nb = reg >> 1, half = reg & 1;
            int unit = ntile * 32 + warpN * 8 + (lane >> 2);
            int j = (nb << 10) + unit;
            int kbase = kts * 16 + half * 8 + (lane & 3) * 2;
            uint32_t pack = 0;
#pragma unroll
            for (int i = 0; i < 2; i++) {
                __half o = __float2half(W_hh[(size_t)j * HID + kbase + i]);
                unsigned short us;
                memcpy(&us, &o, 2);
                pack |= (uint32_t)us << (16 * i);
            }
            out[v] = pack;
        }
    } else {
        // ---- init_h0: A'(step 0) = fp16(h0) ----
        int v = (blockIdx.x - 1024) * blockDim.x + threadIdx.x;
        int e = v * 4;
        float4 h = *(const float4*)(h0 + e);
        float vv[4] = {h.x, h.y, h.z, h.w};
        union { __half b[4]; uint2 u2; } phi;
#pragma unroll
        for (int x = 0; x < 4; x++) phi.b[x] = __float2half(vv[x]);
        *(uint2*)(g_A0 + e) = phi.u2;
    }
}

// ---------------------------------------------------------------------------
// Fused LSTM step: 128x128 HMMA GEMM over K=1024 + in-register cell update.
// 8 warps (2Mx4N, warp tile 64x32), CHUNK=32, NSTAGE=4, B streamed from
// gmem in fragment order, single-pass fp16. cin = c0 (step 0) or g_cbuf.
// ---------------------------------------------------------------------------
__global__ __launch_bounds__(256, 2) void lstm_step_kernel(
    const __half* __restrict__ Acur,
    __half* __restrict__ Anext,          // nullptr on last step
    const float* __restrict__ cin,       // c0 (t=0) or g_cbuf
    const float* __restrict__ obs_t,
    float* __restrict__ hout) {
    extern __shared__ __align__(128) char dyn[];
    const int tid = threadIdx.x;
    const int wid = tid >> 5, lane = tid & 31;
    const int warpM = wid >> 2, warpN = wid & 3;   // 2 x 4 warp grid
    const int bRow = blockIdx.x * TILE_M;

    const uint32_t base = smem_u32(dyn);

    // A ldmatrix per-thread address: rows (g&1)*8+jj of warp's 64, 16B half g>>1
    const int g = lane >> 3, jj = lane & 7;
    const uint32_t aoff = (uint32_t)((warpM * 64 + ((g & 1) << 3) + jj) * ROWB
                                     + ((g >> 1) << 4));

    float acc[4][4][4];
#pragma unroll
    for (int m = 0; m < 4; m++)
#pragma unroll
        for (int n = 0; n < 4; n++)
#pragma unroll
            for (int x = 0; x < 4; x++) acc[m][n][x] = 0.f;

    // A loader: thread covers 32B of row lr at col half lc
    const int lr = tid >> 1;
    const int lc = (tid & 1) * 2;
    const __half* asrc = Acur + (size_t)(bRow + lr) * K1 + lc * 8;
    const uint32_t adst = base + lr * ROWB + lc * 16;

    // B fragment stream pointer: advances 64 uint4 (1KB) per kt-step
    const uint4* bp = g_Wfrag
        + ((size_t)(blockIdx.y * 4 + warpN) * 64 * 32 + lane) * 2;

    // Preload B for kt-step 0
    uint32_t bR[2][8];
    {
        uint4 t0 = bp[0], t1 = bp[1];
        bp += 64;
        bR[0][0] = t0.x; bR[0][1] = t0.y; bR[0][2] = t0.z; bR[0][3] = t0.w;
        bR[0][4] = t1.x; bR[0][5] = t1.y; bR[0][6] = t1.z; bR[0][7] = t1.w;
    }

    // Prologue: A chunks 0..2 into stages 0..2
#pragma unroll
    for (int s = 0; s < NSTAGE - 1; s++) {
        uint32_t so = s * STAGE_BYTES;
        int k0 = s * CHUNK;
        cp16(adst + so, asrc + k0);
        cp16(adst + so + 16, asrc + k0 + 8);
        asm volatile("cp.async.commit_group;" ::: "memory");
    }

#pragma unroll 4
    for (int it = 0; it < NCHUNK; ++it) {
        asm volatile("cp.async.wait_group 2;" ::: "memory");
        __syncthreads();
        const uint32_t so = (uint32_t)(it & (NSTAGE - 1)) * STAGE_BYTES;

        // Prefetch A chunk it+3
        {
            int nl = it + NSTAGE - 1;
            if (nl < NCHUNK) {
                uint32_t so2 = (uint32_t)(nl & (NSTAGE - 1)) * STAGE_BYTES;
                int k0 = nl * CHUNK;
                cp16(adst + so2, asrc + k0);
                cp16(adst + so2 + 16, asrc + k0 + 8);
            }
            asm volatile("cp.async.commit_group;" ::: "memory");
        }

#pragma unroll
        for (int kt = 0; kt < 2; kt++) {
            const int cur = (it * 2 + kt) & 1, nxt = cur ^ 1;

            // Prefetch next kt-step's B fragments (1KB/warp, L2-resident).
            // Padding at the end of g_Wfrag covers the final over-read.
            uint4 t0 = bp[0], t1 = bp[1];
            bp += 64;

            // A fragments for this kt
            uint32_t aF[4][4];
            const uint32_t aA = base + so + aoff + kt * 32;
#pragma unroll
            for (int m = 0; m < 4; m++) ldsm4(aF[m], aA + m * 16 * ROWB);

#pragma unroll
            for (int m = 0; m < 4; m++)
#pragma unroll
                for (int n = 0; n < 4; n++)
                    mma16816(acc[m][n], aF[m], bR[cur][n * 2], bR[cur][n * 2 + 1]);

            bR[nxt][0] = t0.x; bR[nxt][1] = t0.y; bR[nxt][2] = t0.z; bR[nxt][3] = t0.w;
            bR[nxt][4] = t1.x; bR[nxt][5] = t1.y; bR[nxt][6] = t1.z; bR[nxt][7] = t1.w;
        }
    }

    // ------------------ fused LSTM epilogue (all in registers) ------------------
    const int q = lane & 3;
    const int u0 = blockIdx.y * 32 + warpN * 8 + 2 * q;    // 2 units: u0, u0+1
    const int rbase = bRow + warpM * 64 + (lane >> 2);

    float wcx[2][4], wcy[2][4], bcv[2][4];
#pragma unroll
    for (int i = 0; i < 2; i++)
#pragma unroll
        for (int gg = 0; gg < 4; gg++) {
            int j = (gg << 10) + u0 + i;
            float2 w = *(const float2*)(g_Wc + j * 2);
            wcx[i][gg] = w.x; wcy[i][gg] = w.y; bcv[i][gg] = g_bc[j];
        }

#pragma unroll
    for (int m = 0; m < 4; m++)
#pragma unroll
        for (int s = 0; s < 2; s++) {
            int b = rbase + m * 16 + s * 8;
            float2 ob = *(const float2*)(obs_t + b * 2);
            float2 cold = *(const float2*)(cin + (size_t)b * HID + u0);
            float cprev[2] = {cold.x, cold.y};
            float cn[2], hn[2];
#pragma unroll
            for (int i = 0; i < 2; i++) {
                float gv[4];
#pragma unroll
                for (int gg = 0; gg < 4; gg++)
                    gv[gg] = acc[m][gg][s * 2 + i]
                           + ob.x * wcx[i][gg] + ob.y * wcy[i][gg] + bcv[i][gg];
                float ig = sigm(gv[0]);
                float fg = sigm(gv[1]);
                float gc = tanh_f(gv[2]);
                float og = sigm(gv[3]);
                cn[i] = fg * cprev[i] + ig * gc;
                hn[i] = og * tanh_f(cn[i]);
            }
            *(float2*)(g_cbuf + (size_t)b * HID + u0) = make_float2(cn[0], cn[1]);
            if (hout)
                *(float2*)(hout + (size_t)b * HID + u0) = make_float2(hn[0], hn[1]);

            if (Anext) {
                union { __half h[2]; uint32_t u; } phi;
#pragma unroll
                for (int i = 0; i < 2; i++) phi.h[i] = __float2half(hn[i]);
                *(uint32_t*)(Anext + (size_t)b * K1 + u0) = phi.u;
            }
        }
}

// ---------------------------------------------------------------------------
extern "C" void kernel_launch(void* const* d_in, const int* in_sizes, int n_in,
                              void* d_out, int out_size) {
    const float* obs   = (const float*)d_in[0];
    const float* h0    = (const float*)d_in[1];
    const float* c0    = (const float*)d_in[2];
    const float* W_emb = (const float*)d_in[3];
    const float* b_emb = (const float*)d_in[4];
    const float* W_ih  = (const float*)d_in[5];
    const float* W_hh  = (const float*)d_in[6];
    const float* b_ih  = (const float*)d_in[7];
    const float* b_hh  = (const float*)d_in[8];

    float* cbuf;
    __half *a0, *a1;
    cudaGetSymbolAddress((void**)&cbuf, g_cbuf);
    cudaGetSymbolAddress((void**)&a0, g_A0);
    cudaGetSymbolAddress((void**)&a1, g_A1);

    prep_all_kernel<<<3072, 256>>>(W_emb, b_emb, W_ih, b_ih, b_hh, W_hh, h0);

    cudaFuncSetAttribute(lstm_step_kernel,
                         cudaFuncAttributeMaxDynamicSharedMemorySize, SMEM_DYN);

    dim3 grid(BATCH / TILE_M, HID / 32);   // (16, 32)
    __half* bufs[2] = {a0, a1};
    for (int t = 0; t < OBS_LEN; t++) {
        const float* cin = (t == 0) ? c0 : cbuf;
        __half* Anext = (t == OBS_LEN - 1) ? nullptr : bufs[(t + 1) & 1];
        lstm_step_kernel<<<grid, 256, SMEM_DYN>>>(
            bufs[t & 1], Anext, cin,
            obs + (size_t)t * BATCH * 2,
            (t == OBS_LEN - 1) ? (float*)d_out : nullptr);
    }
}

// round 15
// speedup vs baseline: 1.5237x; 1.0065x over previous
#include <cuda_runtime.h>
#include <cuda_fp16.h>
#include <math.h>
#include <stdint.h>
#include <string.h>

#define OBS_LEN 20
#define BATCH   2048
#define IN_DIM  512
#define HID     1024
#define G4      4096
#define K1      1024          // single-pass fp16: A' = fp16(h), B' = fp16(W)
#define CHUNK   32            // K per pipeline chunk
#define NCHUNK  32            // K1/CHUNK
#define NROUND  16            // chunk pairs per step
#define TILE_M  128
#define ROWB    80            // A smem row stride (64 data + 16 pad)
#define STAGE_BYTES (128 * ROWB)          // A-only stage: 10240
#define NSTAGE  8
#define SMEM_DYN (NSTAGE * STAGE_BYTES)   // 81920 (2 CTAs = 160KB <= 228KB)

// ---------------------------------------------------------------------------
// Device scratch
// ---------------------------------------------------------------------------
__device__ __align__(16) float   g_Wc[G4 * 2];
__device__ __align__(16) float   g_bc[G4];
// B in mma-fragment order: [wb=ntile*4+warpN][ktstep=0..63][lane][8 regs]
// + 64 uint4 padding (one extra kt-step) for the tail prefetch.
#define WFRAG_U4 ((size_t)128 * 64 * 32 * 2 + 64)
__device__ __align__(16) uint4   g_Wfrag[WFRAG_U4];          // ~8.4 MB
__device__ __align__(16) __half  g_A0[(size_t)BATCH * K1];   // 4.2 MB
__device__ __align__(16) __half  g_A1[(size_t)BATCH * K1];
__device__ __align__(16) float   g_cbuf[(size_t)BATCH * HID];

// ---------------------------------------------------------------------------
// Helpers (family-portable PTX only: cp.async / ldmatrix / mma.sync / tanh.approx)
// ---------------------------------------------------------------------------
__device__ __forceinline__ uint32_t smem_u32(const void* p) {
    uint32_t a;
    asm("{ .reg .u64 t; cvta.to.shared.u64 t, %1; cvt.u32.u64 %0, t; }"
        : "=r"(a) : "l"(p));
    return a;
}
__device__ __forceinline__ void cp16(uint32_t dst, const void* src) {
    asm volatile("cp.async.cg.shared.global [%0], [%1], 16;"
                 :: "r"(dst), "l"(src) : "memory");
}
__device__ __forceinline__ void ldsm4(uint32_t* r, uint32_t addr) {
    asm volatile("ldmatrix.sync.aligned.m8n8.x4.shared.b16 {%0,%1,%2,%3}, [%4];"
                 : "=r"(r[0]), "=r"(r[1]), "=r"(r[2]), "=r"(r[3]) : "r"(addr));
}
__device__ __forceinline__ void mma16816(float* d, const uint32_t* a,
                                         uint32_t b0, uint32_t b1) {
    asm volatile(
        "mma.sync.aligned.m16n8k16.row.col.f32.f16.f16.f32 "
        "{%0,%1,%2,%3},{%4,%5,%6,%7},{%8,%9},{%0,%1,%2,%3};"
        : "+f"(d[0]), "+f"(d[1]), "+f"(d[2]), "+f"(d[3])
        : "r"(a[0]), "r"(a[1]), "r"(a[2]), "r"(a[3]), "r"(b0), "r"(b1));
}
// HW tanh unit (MUFU.TANH, sm_75+): 1 MUFU op, ~2^-11 rel accuracy.
__device__ __forceinline__ float tanh_ap(float x) {
    float y;
    asm("tanh.approx.f32 %0, %1;" : "=f"(y) : "f"(x));
    return y;
}
__device__ __forceinline__ float sigm(float x) {
    return fmaf(0.5f, tanh_ap(0.5f * x), 0.5f);
}
__device__ __forceinline__ float tanh_f(float x) { return tanh_ap(x); }

// ---------------------------------------------------------------------------
// Merged prep (one launch, 3072 blocks x 256):
//   blocks [0,512)     : fold embedding -> Wc [G4][2], bc [G4]
//   blocks [512,1024)  : B' = fp16(W_hh) in exact mma b-fragment order
//   blocks [1024,3072) : A'(step 0) = fp16(h0)
// ---------------------------------------------------------------------------
__global__ void prep_all_kernel(const float* __restrict__ W_emb,
                                const float* __restrict__ b_emb,
                                const float* __restrict__ W_ih,
                                const float* __restrict__ b_ih,
                                const float* __restrict__ b_hh,
                                const float* __restrict__ W_hh,
                                const float* __restrict__ h0) {
    if (blockIdx.x < 512) {
        int warp = (blockIdx.x * blockDim.x + threadIdx.x) >> 5;
        int lane = threadIdx.x & 31;
        if (warp >= G4) return;
        const float* wrow = W_ih + (size_t)warp * IN_DIM;
        float s0 = 0.f, s1 = 0.f, sb = 0.f;
        for (int h = lane; h < IN_DIM; h += 32) {
            float w = wrow[h];
            s0 += w * W_emb[h * 2 + 0];
            s1 += w * W_emb[h * 2 + 1];
            sb += w * b_emb[h];
        }
#pragma unroll
        for (int o = 16; o > 0; o >>= 1) {
            s0 += __shfl_down_sync(0xffffffffu, s0, o);
            s1 += __shfl_down_sync(0xffffffffu, s1, o);
            sb += __shfl_down_sync(0xffffffffu, sb, o);
        }
        if (lane == 0) {
            g_Wc[warp * 2 + 0] = s0;
            g_Wc[warp * 2 + 1] = s1;
            g_bc[warp] = sb + b_ih[warp] + b_hh[warp];
        }
    } else if (blockIdx.x < 1024) {
        int bid = blockIdx.x - 512;
        int wb = bid >> 2;                 // 0..127
        int vbase = (bid & 3) * 4096;      // quarter of 16384
        int ntile = wb >> 2, warpN = wb & 3;
        uint32_t* out = (uint32_t*)g_Wfrag + (size_t)wb * 16384;
        for (int v = vbase + threadIdx.x; v < vbase + 4096; v += blockDim.x) {
            int reg   = v & 7;
            int lane  = (v >> 3) & 31;
            int kts   = v >> 8;            // 0..63
            int nb = reg >> 1, half = reg & 1;
            int unit = ntile * 32 + warpN * 8 + (lane >> 2);
            int j = (nb << 10) + unit;
            int kbase = kts * 16 + half * 8 + (lane & 3) * 2;
            uint32_t pack = 0;
#pragma unroll
            for (int i = 0; i < 2; i++) {
                __half o = __float2half(W_hh[(size_t)j * HID + kbase + i]);
                unsigned short us;
                memcpy(&us, &o, 2);
                pack |= (uint32_t)us << (16 * i);
            }
            out[v] = pack;
        }
    } else {
        int v = (blockIdx.x - 1024) * blockDim.x + threadIdx.x;
        int e = v * 4;
        float4 h = *(const float4*)(h0 + e);
        float vv[4] = {h.x, h.y, h.z, h.w};
        union { __half b[4]; uint2 u2; } phi;
#pragma unroll
        for (int x = 0; x < 4; x++) phi.b[x] = __float2half(vv[x]);
        *(uint2*)(g_A0 + e) = phi.u2;
    }
}

// ---------------------------------------------------------------------------
// Fused LSTM step: 128x128 HMMA GEMM over K=1024 + in-register cell update.
// 8 warps (2Mx4N, warp tile 64x32), paired-chunk pipeline: 16 rounds of
// (1 wait_group + 1 __syncthreads + 2 chunks of compute), NSTAGE=8.
// ---------------------------------------------------------------------------
__global__ __launch_bounds__(256, 2) void lstm_step_kernel(
    const __half* __restrict__ Acur,
    __half* __restrict__ Anext,          // nullptr on last step
    const float* __restrict__ cin,       // c0 (t=0) or g_cbuf
    const float* __restrict__ obs_t,
    float* __restrict__ hout) {
    extern __shared__ __align__(128) char dyn[];
    const int tid = threadIdx.x;
    const int wid = tid >> 5, lane = tid & 31;
    const int warpM = wid >> 2, warpN = wid & 3;   // 2 x 4 warp grid
    const int bRow = blockIdx.x * TILE_M;

    const uint32_t base = smem_u32(dyn);

    // A ldmatrix per-thread address: rows (g&1)*8+jj of warp's 64, 16B half g>>1
    const int g = lane >> 3, jj = lane & 7;
    const uint32_t aoff = (uint32_t)((warpM * 64 + ((g & 1) << 3) + jj) * ROWB
                                     + ((g >> 1) << 4));

    float acc[4][4][4];
#pragma unroll
    for (int m = 0; m < 4; m++)
#pragma unroll
        for (int n = 0; n < 4; n++)
#pragma unroll
            for (int x = 0; x < 4; x++) acc[m][n][x] = 0.f;

    // A loader: thread covers 32B of row lr at col half lc
    const int lr = tid >> 1;
    const int lc = (tid & 1) * 2;
    const __half* asrc = Acur + (size_t)(bRow + lr) * K1 + lc * 8;
    const uint32_t adst = base + lr * ROWB + lc * 16;

    // B fragment stream pointer: advances 64 uint4 (1KB) per kt-step
    const uint4* bp = g_Wfrag
        + ((size_t)(blockIdx.y * 4 + warpN) * 64 * 32 + lane) * 2;

    // Preload B for kt-step 0
    uint32_t bR[2][8];
    {
        uint4 t0 = bp[0], t1 = bp[1];
        bp += 64;
        bR[0][0] = t0.x; bR[0][1] = t0.y; bR[0][2] = t0.z; bR[0][3] = t0.w;
        bR[0][4] = t1.x; bR[0][5] = t1.y; bR[0][6] = t1.z; bR[0][7] = t1.w;
    }

    // Prologue: chunks 0..3 into stages 0..3, committed as 2 groups of 2
#pragma unroll
    for (int s = 0; s < 4; s++) {
        uint32_t so = s * STAGE_BYTES;
        int k0 = s * CHUNK;
        cp16(adst + so, asrc + k0);
        cp16(adst + so + 16, asrc + k0 + 8);
        if (s & 1) asm volatile("cp.async.commit_group;" ::: "memory");
    }

#pragma unroll 4
    for (int r = 0; r < NROUND; ++r) {
        asm volatile("cp.async.wait_group 1;" ::: "memory");
        __syncthreads();

        // Prefetch chunks 2r+4, 2r+5 into stages (2r+4)&7, (2r+5)&7 (1 group)
        if (r < NROUND - 2) {
#pragma unroll
            for (int p = 0; p < 2; p++) {
                int ch = 2 * r + 4 + p;
                uint32_t so2 = (uint32_t)(ch & (NSTAGE - 1)) * STAGE_BYTES;
                int k0 = ch * CHUNK;
                cp16(adst + so2, asrc + k0);
                cp16(adst + so2 + 16, asrc + k0 + 8);
            }
        }
        asm volatile("cp.async.commit_group;" ::: "memory");

        // Compute chunks 2r and 2r+1 (stages (2r)&7, (2r+1)&7)
#pragma unroll
        for (int half = 0; half < 2; half++) {
            const uint32_t so =
                (uint32_t)((2 * r + half) & (NSTAGE - 1)) * STAGE_BYTES;
#pragma unroll
            for (int kt = 0; kt < 2; kt++) {
                const int cur = ((2 * r + half) * 2 + kt) & 1, nxt = cur ^ 1;

                // Prefetch next kt-step's B fragments (1KB/warp, L2-resident).
                uint4 t0 = bp[0], t1 = bp[1];
                bp += 64;

                // A fragments for this kt
                uint32_t aF[4][4];
                const uint32_t aA = base + so + aoff + kt * 32;
#pragma unroll
                for (int m = 0; m < 4; m++) ldsm4(aF[m], aA + m * 16 * ROWB);

#pragma unroll
                for (int m = 0; m < 4; m++)
#pragma unroll
                    for (int n = 0; n < 4; n++)
                        mma16816(acc[m][n], aF[m],
                                 bR[cur][n * 2], bR[cur][n * 2 + 1]);

                bR[nxt][0] = t0.x; bR[nxt][1] = t0.y;
                bR[nxt][2] = t0.z; bR[nxt][3] = t0.w;
                bR[nxt][4] = t1.x; bR[nxt][5] = t1.y;
                bR[nxt][6] = t1.z; bR[nxt][7] = t1.w;
            }
        }
    }

    // ------------------ fused LSTM epilogue (all in registers) ------------------
    const int q = lane & 3;
    const int u0 = blockIdx.y * 32 + warpN * 8 + 2 * q;    // 2 units: u0, u0+1
    const int rbase = bRow + warpM * 64 + (lane >> 2);

    float wcx[2][4], wcy[2][4], bcv[2][4];
#pragma unroll
    for (int i = 0; i < 2; i++)
#pragma unroll
        for (int gg = 0; gg < 4; gg++) {
            int j = (gg << 10) + u0 + i;
            float2 w = *(const float2*)(g_Wc + j * 2);
            wcx[i][gg] = w.x; wcy[i][gg] = w.y; bcv[i][gg] = g_bc[j];
        }

#pragma unroll
    for (int m = 0; m < 4; m++)
#pragma unroll
        for (int s = 0; s < 2; s++) {
            int b = rbase + m * 16 + s * 8;
            float2 ob = *(const float2*)(obs_t + b * 2);
            float2 cold = *(const float2*)(cin + (size_t)b * HID + u0);
            float cprev[2] = {cold.x, cold.y};
            float cn[2], hn[2];
#pragma unroll
            for (int i = 0; i < 2; i++) {
                float gv[4];
#pragma unroll
                for (int gg = 0; gg < 4; gg++)
                    gv[gg] = acc[m][gg][s * 2 + i]
                           + ob.x * wcx[i][gg] + ob.y * wcy[i][gg] + bcv[i][gg];
                float ig = sigm(gv[0]);
                float fg = sigm(gv[1]);
                float gc = tanh_f(gv[2]);
                float og = sigm(gv[3]);
                cn[i] = fg * cprev[i] + ig * gc;
                hn[i] = og * tanh_f(cn[i]);
            }
            if (Anext) {
                // c needed by the next step
                *(float2*)(g_cbuf + (size_t)b * HID + u0) =
                    make_float2(cn[0], cn[1]);
                union { __half h[2]; uint32_t u; } phi;
#pragma unroll
                for (int i = 0; i < 2; i++) phi.h[i] = __float2half(hn[i]);
                *(uint32_t*)(Anext + (size_t)b * K1 + u0) = phi.u;
            }
            if (hout)
                *(float2*)(hout + (size_t)b * HID + u0) = make_float2(hn[0], hn[1]);
        }
}

// ---------------------------------------------------------------------------
extern "C" void kernel_launch(void* const* d_in, const int* in_sizes, int n_in,
                              void* d_out, int out_size) {
    const float* obs   = (const float*)d_in[0];
    const float* h0    = (const float*)d_in[1];
    const float* c0    = (const float*)d_in[2];
    const float* W_emb = (const float*)d_in[3];
    const float* b_emb = (const float*)d_in[4];
    const float* W_ih  = (const float*)d_in[5];
    const float* W_hh  = (const float*)d_in[6];
    const float* b_ih  = (const float*)d_in[7];
    const float* b_hh  = (const float*)d_in[8];

    float* cbuf;
    __half *a0, *a1;
    cudaGetSymbolAddress((void**)&cbuf, g_cbuf);
    cudaGetSymbolAddress((void**)&a0, g_A0);
    cudaGetSymbolAddress((void**)&a1, g_A1);

    prep_all_kernel<<<3072, 256>>>(W_emb, b_emb, W_ih, b_ih, b_hh, W_hh, h0);

    cudaFuncSetAttribute(lstm_step_kernel,
                         cudaFuncAttributeMaxDynamicSharedMemorySize, SMEM_DYN);

    dim3 grid(BATCH / TILE_M, HID / 32);   // (16, 32)
    __half* bufs[2] = {a0, a1};
    for (int t = 0; t < OBS_LEN; t++) {
        const float* cin = (t == 0) ? c0 : cbuf;
        __half* Anext = (t == OBS_LEN - 1) ? nullptr : bufs[(t + 1) & 1];
        lstm_step_kernel<<<grid, 256, SMEM_DYN>>>(
            bufs[t & 1], Anext, cin,
            obs + (size_t)t * BATCH * 2,
            (t == OBS_LEN - 1) ? (float*)d_out : nullptr);
    }
}